// round 15
// baseline (speedup 1.0000x reference)
#include <cuda_runtime.h>
#include <cuda_fp16.h>
#include <math.h>
#include <stdint.h>

// ---------------- problem constants ----------------
#define B_   2
#define T_   2048
#define D_   2048
#define H_   16
#define HKV_ 4
#define HD_  128
#define DKV_ (HKV_*HD_)    // 512
#define NQKV 3072          // fused q|k|v projection width
#define MROWS (B_*T_)      // 4096
#define QSCALE ((float)(1.4426950408889634 * 0.08838834764831845))
#define SOFF  8.0f         // static softmax offset (log2 units); O/l ratio invariant

// ---------------- scratch (device globals) ----------------
__device__ __align__(16) __half g_xh   [(size_t)MROWS * D_];    // x in fp16
__device__ __align__(16) __half g_wcatT[(size_t)NQKV * D_];     // [Wq|Wk|Wv]^T fp16: [n][k]
__device__ __align__(16) __half g_worT [(size_t)D_ * D_];       // Wo^T fp16: [n][k]
__device__ __align__(16) __half g_qr   [(size_t)B_*H_*T_*HD_];  // Q roped, (bh,t,d)
__device__ __align__(16) __half g_kr   [(size_t)B_*HKV_*T_*HD_];// K roped
__device__ __align__(16) __half g_vT   [(size_t)B_*HKV_*HD_*T_];// V^T, (bkh,d,t)
__device__ __align__(16) __half g_attn [(size_t)MROWS * D_];    // attention out fp16
__device__ float g_cos_t[T_*64];
__device__ float g_sin_t[T_*64];

// ---------------- helpers ----------------
__device__ __forceinline__ uint32_t smem_u32(const void* p) {
    return (uint32_t)__cvta_generic_to_shared(p);
}
__device__ __forceinline__ void cp_async16(uint32_t dst, const void* src) {
    asm volatile("cp.async.cg.shared.global [%0], [%1], 16;\n" :: "r"(dst), "l"(src));
}
__device__ __forceinline__ void mma_f16(float* c, const uint32_t* a, uint32_t b0, uint32_t b1) {
    asm volatile(
        "mma.sync.aligned.m16n8k16.row.col.f32.f16.f16.f32 "
        "{%0,%1,%2,%3}, {%4,%5,%6,%7}, {%8,%9}, {%0,%1,%2,%3};\n"
        : "+f"(c[0]), "+f"(c[1]), "+f"(c[2]), "+f"(c[3])
        : "r"(a[0]), "r"(a[1]), "r"(a[2]), "r"(a[3]), "r"(b0), "r"(b1));
}
__device__ __forceinline__ void ldsm4(uint32_t& r0, uint32_t& r1, uint32_t& r2, uint32_t& r3,
                                      uint32_t addr) {
    asm volatile("ldmatrix.sync.aligned.m8n8.x4.shared.b16 {%0,%1,%2,%3}, [%4];"
        : "=r"(r0), "=r"(r1), "=r"(r2), "=r"(r3) : "r"(addr));
}
__device__ __forceinline__ uint32_t h2u(float a, float b) {
    __half2 h = __floats2half2_rn(a, b);
    return *(uint32_t*)&h;
}
__device__ __forceinline__ float ex2f(float x) {
    float r;
    asm("ex2.approx.f32 %0, %1;" : "=f"(r) : "f"(x));
    return r;
}

// ---------------- RoPE table (fp64 precompute) ----------------
__global__ void rope_table_kernel() {
    int t = blockIdx.x;
    int i = threadIdx.x;                       // 0..63
    double inv = exp(-((double)(2*i) / 128.0) * 9.210340371976182736);
    double ang = (double)t * inv;
    g_cos_t[t*64 + i] = (float)cos(ang);
    g_sin_t[t*64 + i] = (float)sin(ang);
}

// ---------------- fused prep: x f32->f16 + all 4 weight transposes ----------------
// blocks [0, 8192): elementwise convert of x (8192*256 float4 == 2M == exact)
// blocks [8192, 18432): 32x32 transpose tiles of Wq|Wk|Wv|Wo.
__global__ void prep_all(const float4* __restrict__ x4, __half2* __restrict__ xh2,
                         const float* __restrict__ Wq, const float* __restrict__ Wk,
                         const float* __restrict__ Wv, const float* __restrict__ Wo,
                         __half* __restrict__ wcatT, __half* __restrict__ worT) {
    if (blockIdx.x < 8192) {
        int i = blockIdx.x * 256 + threadIdx.x;
        float4 v = x4[i];
        xh2[2*i]     = __floats2half2_rn(v.x, v.y);
        xh2[2*i + 1] = __floats2half2_rn(v.z, v.w);
        return;
    }
    __shared__ float S[32][33];
    int tile = blockIdx.x - 8192;
    const float* in;
    __half* out;
    int cols, n0, k0;
    if (tile < 4096)      { int t = tile;        in = Wq; out = wcatT;                   cols = D_;   n0 = (t & 63) << 5; k0 = (t >> 6) << 5; }
    else if (tile < 5120) { int t = tile - 4096; in = Wk; out = wcatT + (size_t)2048*D_; cols = DKV_; n0 = (t & 15) << 5; k0 = (t >> 4) << 5; }
    else if (tile < 6144) { int t = tile - 5120; in = Wv; out = wcatT + (size_t)2560*D_; cols = DKV_; n0 = (t & 15) << 5; k0 = (t >> 4) << 5; }
    else                  { int t = tile - 6144; in = Wo; out = worT;                    cols = D_;   n0 = (t & 63) << 5; k0 = (t >> 6) << 5; }
    for (int e = threadIdx.x; e < 1024; e += 256) {
        int r = e >> 5, c = e & 31;
        S[r][c] = in[(size_t)(k0 + r)*cols + n0 + c];
    }
    __syncthreads();
    for (int e = threadIdx.x; e < 1024; e += 256) {
        int r = e >> 5, c = e & 31;
        out[(size_t)(n0 + r)*D_ + k0 + c] = __float2half_rn(S[c][r]);
    }
}

// ---------------- GEMM: 128x128 CTA tile, BK=64, 3-stage ring, 1 barrier/iter ----------------
#define ASTR 72                                  // padded row stride (halfs), 144B: conflict-free
#define STG_HALFS (2*128*ASTR)                   // A tile + B tile per stage (18432)
#define GM_SMEM   (3*STG_HALFS*2)                // bytes (110592) -> 2 CTA/SM

__device__ __forceinline__ void gemm_issue(const __half* __restrict__ Ag,
                                           const __half* __restrict__ Bg,
                                           uint32_t sbase, int K, int tid) {
    uint32_t sB = sbase + 128*ASTR*2;
#pragma unroll
    for (int i = 0; i < 4; ++i) {                // A: 128 rows x 8 chunks of 16B
        int c = tid + (i << 8);
        int r = c >> 3, cb = (c & 7) << 3;
        cp_async16(sbase + (r*ASTR + cb)*2, Ag + (size_t)r*K + cb);
    }
#pragma unroll
    for (int i = 0; i < 4; ++i) {                // B: 128 rows x 8 chunks
        int c = tid + (i << 8);
        int r = c >> 3, cb = (c & 7) << 3;
        cp_async16(sB + (r*ASTR + cb)*2, Bg + (size_t)r*K + cb);
    }
    asm volatile("cp.async.commit_group;\n");
}

// mainloop shared by both GEMMs; declares acc[2][8][4]. BK=64, 4 ksteps/iter,
// single barrier per iter; ring of 3 stages, wait_group(1) keeps 1 load in flight.
#define GEMM_MAIN(A, Bt, K)                                                        \
    int lrow = lane & 15, lcol = (lane >> 4) << 3;                                 \
    uint32_t aoff[2], boff[4];                                                     \
    _Pragma("unroll")                                                              \
    for (int mt = 0; mt < 2; ++mt)                                                 \
        aoff[mt] = (uint32_t)(((wm + (mt << 4) + lrow)*ASTR + lcol)*2);            \
    _Pragma("unroll")                                                              \
    for (int p = 0; p < 4; ++p) {                                                  \
        int brow = bmap(p);                                                        \
        boff[p] = (uint32_t)(((128 + brow)*ASTR + lcol)*2);                        \
    }                                                                              \
    const __half* Abase = (A)  + (size_t)row0 * (K);                               \
    const __half* Bbase = (Bt) + (size_t)col0 * (K);                               \
    float acc[2][8][4];                                                            \
    _Pragma("unroll")                                                              \
    for (int mt = 0; mt < 2; ++mt)                                                 \
        _Pragma("unroll")                                                          \
        for (int nt = 0; nt < 8; ++nt)                                             \
            _Pragma("unroll")                                                      \
            for (int r = 0; r < 4; ++r) acc[mt][nt][r] = 0.f;                      \
    int iters = (K) / 64;                                                          \
    gemm_issue(Abase,      Bbase,      sbase,             (K), tid);               \
    gemm_issue(Abase + 64, Bbase + 64, sbase + STG_HALFS*2, (K), tid);             \
    for (int it = 0; it < iters; ++it) {                                           \
        if (it + 2 < iters) {                                                      \
            asm volatile("cp.async.wait_group %0;\n" :: "n"(1));                   \
        } else {                                                                   \
            asm volatile("cp.async.wait_group %0;\n" :: "n"(0));                   \
        }                                                                          \
        __syncthreads();                                                           \
        if (it + 2 < iters)                                                        \
            gemm_issue(Abase + (it+2)*64, Bbase + (it+2)*64,                       \
                       sbase + ((it+2) % 3)*STG_HALFS*2, (K), tid);                \
        uint32_t stg = sbase + (it % 3)*STG_HALFS*2;                               \
        _Pragma("unroll")                                                          \
        for (int ks = 0; ks < 4; ++ks) {                                           \
            uint32_t kb = stg + ks*32;                                             \
            uint32_t a[2][4], b[8][2];                                             \
            ldsm4(a[0][0], a[0][1], a[0][2], a[0][3], kb + aoff[0]);               \
            ldsm4(a[1][0], a[1][1], a[1][2], a[1][3], kb + aoff[1]);               \
            _Pragma("unroll")                                                      \
            for (int p = 0; p < 4; ++p)                                            \
                ldsm4(b[2*p][0], b[2*p+1][0], b[2*p][1], b[2*p+1][1], kb + boff[p]);\
            _Pragma("unroll")                                                      \
            for (int mt = 0; mt < 2; ++mt)                                         \
                _Pragma("unroll")                                                  \
                for (int nt = 0; nt < 8; ++nt)                                     \
                    mma_f16(acc[mt][nt], a[mt], b[nt][0], b[nt][1]);               \
        }                                                                          \
    }

// ---------------- Wo GEMM: C f32 = A @ Bt^T ----------------
__global__ __launch_bounds__(256, 2)
void gemm_f16(const __half* __restrict__ A, const __half* __restrict__ Bt,
              float* __restrict__ C, int K, int ldc) {
    extern __shared__ __half smh[];
    uint32_t sbase = smem_u32(smh);
    int tid  = threadIdx.x;
    int lane = tid & 31, wid = tid >> 5;
    int g = lane >> 2, tig = lane & 3;
    int wm = (wid >> 1) << 5;
    int wn = (wid & 1) << 6;
    int row0 = blockIdx.y << 7;
    int col0 = blockIdx.x << 7;

    #define bmap(p) (wn + ((p) << 4) + (lane & 15))
    GEMM_MAIN(A, Bt, K)
    #undef bmap

#pragma unroll
    for (int mt = 0; mt < 2; ++mt) {
#pragma unroll
        for (int nt = 0; nt < 8; ++nt) {
            int r    = row0 + wm + (mt << 4) + g;
            int ccol = col0 + wn + (nt << 3) + (tig << 1);
            *(float2*)(C + (size_t)r*ldc + ccol)       = make_float2(acc[mt][nt][0], acc[mt][nt][1]);
            *(float2*)(C + (size_t)(r + 8)*ldc + ccol) = make_float2(acc[mt][nt][2], acc[mt][nt][3]);
        }
    }
}

// ---------------- QKV GEMM with fused RoPE/layout epilogue ----------------
__global__ __launch_bounds__(256, 2)
void gemm_qkv(const __half* __restrict__ A, const __half* __restrict__ Bt,
              __half* __restrict__ qrOut, __half* __restrict__ krOut,
              __half* __restrict__ vtOut) {
    extern __shared__ __half smh[];
    uint32_t sbase = smem_u32(smh);
    int tid  = threadIdx.x;
    int lane = tid & 31, wid = tid >> 5;
    int g = lane >> 2, tig = lane & 3;
    int wm = (wid >> 1) << 5;
    int wn8 = (wid & 1) << 3;
    int row0 = blockIdx.y << 7;
    int col0 = blockIdx.x << 7;

    #define bmap(p) (wn8 + ((p) << 5) + ((lane & 8) << 1) + (lane & 7))
    GEMM_MAIN(A, Bt, D_)
    #undef bmap

    // -------- fused epilogue --------
    int head  = blockIdx.x;             // tile width 128 == one head
    int trow0 = row0 & (T_ - 1);
    int bb    = row0 >> 11;

    if (head < 20) {
        float scale = (head < 16) ? QSCALE : 1.0f;
        __half* obase = (head < 16)
            ? qrOut + ((size_t)(bb*H_   + head     )*T_ + trow0)*HD_
            : krOut + ((size_t)(bb*HKV_ + head - 16)*T_ + trow0)*HD_;
#pragma unroll
        for (int mt = 0; mt < 2; ++mt) {
#pragma unroll
            for (int rh = 0; rh < 2; ++rh) {
                int r = wm + (mt << 4) + g + (rh << 3);
                int t = trow0 + r;
                int i0 = rh << 1;
#pragma unroll
                for (int nt = 0; nt < 4; ++nt) {
                    int dm = wn8 + (nt << 4) + (tig << 1);
                    float2 cv = *(const float2*)&g_cos_t[t*64 + dm];
                    float2 sv = *(const float2*)&g_sin_t[t*64 + dm];
                    float a0 = acc[mt][nt][i0],     a1 = acc[mt][nt][i0+1];
                    float b0 = acc[mt][nt+4][i0],   b1 = acc[mt][nt+4][i0+1];
                    uint32_t lo = h2u((a0*cv.x - b0*sv.x)*scale,
                                      (a1*cv.y - b1*sv.y)*scale);
                    uint32_t hi = h2u((b0*cv.x + a0*sv.x)*scale,
                                      (b1*cv.y + a1*sv.y)*scale);
                    *(uint32_t*)&obase[(size_t)r*HD_ + dm]      = lo;
                    *(uint32_t*)&obase[(size_t)r*HD_ + dm + 64] = hi;
                }
            }
        }
    } else {
        // V: transpose through smem, write (bkh, d, t)
        __syncthreads();
        __half* S2 = smh;
#pragma unroll
        for (int mt = 0; mt < 2; ++mt)
#pragma unroll
            for (int nt = 0; nt < 8; ++nt) {
                int r = wm + (mt << 4) + g;
                int c = wn8 + (nt << 4) + (tig << 1);
                S2[(c    )*132 + r    ] = __float2half_rn(acc[mt][nt][0]);
                S2[(c + 1)*132 + r    ] = __float2half_rn(acc[mt][nt][1]);
                S2[(c    )*132 + r + 8] = __float2half_rn(acc[mt][nt][2]);
                S2[(c + 1)*132 + r + 8] = __float2half_rn(acc[mt][nt][3]);
            }
        __syncthreads();
        __half* obase = vtOut + ((size_t)(bb*HKV_ + head - 20)*HD_)*T_ + trow0;
#pragma unroll
        for (int d = wid; d < 128; d += 8) {
            uint32_t w0 = *(uint32_t*)&S2[d*132 + 2*lane];
            uint32_t w1 = *(uint32_t*)&S2[d*132 + 64 + 2*lane];
            *(uint32_t*)&obase[(size_t)d*T_ + 2*lane]      = w0;
            *(uint32_t*)&obase[(size_t)d*T_ + 64 + 2*lane] = w1;
        }
    }
}

// ---------------- flash attention: 128-wide k-tiles, static-offset softmax ----------------
// S-phase p-outer: each n-tile-pair finishes its mma chain then immediately does
// mask+ex2(f32)+pack, overlapping MUFU of pair p with tensor work of pair p+1.
#define FK_STR 136
#define FV_STR 136
#define FKS0 0
#define FKS1 (128*FK_STR)                  // 17408
#define FVT0 (2*128*FK_STR)                // 34816
#define FVT1 (FVT0 + 128*FV_STR)           // 52224
#define FSM_BYTES ((FVT1 + 128*FV_STR)*2)  // 139264
#define ONE2 0x3C003C00u                   // half2(1.0, 1.0)

__device__ __forceinline__ void fa_issue(const __half* __restrict__ kbase,
                                         const __half* __restrict__ vbase,
                                         uint32_t sbase, int buf, int k0, int tid) {
    uint32_t ks = sbase + (buf ? FKS1 : FKS0)*2;
    uint32_t vt = sbase + (buf ? FVT1 : FVT0)*2;
#pragma unroll
    for (int i = 0; i < 8; ++i) {                 // K: 128 rows x 16 chunks
        int c = tid + (i << 8);
        int row = c >> 4, cb = (c & 15) << 3;
        cp_async16(ks + (row*FK_STR + cb)*2, kbase + (size_t)(k0 + row)*HD_ + cb);
    }
#pragma unroll
    for (int i = 0; i < 8; ++i) {                 // V^T: 128 d-rows x 16 t-chunks
        int c = tid + (i << 8);
        int d = c >> 4, cb = (c & 15) << 3;
        cp_async16(vt + (d*FV_STR + cb)*2, vbase + (size_t)d*T_ + k0 + cb);
    }
    asm volatile("cp.async.commit_group;\n");
}

__global__ __launch_bounds__(256, 1)
void flash_f16(const __half* __restrict__ qr, const __half* __restrict__ kr,
               const __half* __restrict__ vT, __half* __restrict__ attn) {
    extern __shared__ __half smh[];
    uint32_t sbase = smem_u32(smh);

    int tid = threadIdx.x, lane = tid & 31, wid = tid >> 5;
    int g = lane >> 2, tig = lane & 3;
    int qi = gridDim.x - 1 - blockIdx.x;          // heavy tiles first
    int q0 = qi << 7;
    int bh = blockIdx.y;
    int b = bh >> 4, h = bh & 15, kvh = h >> 2;
    int nkt = qi + 1;                             // 128-wide k tiles

    const __half* qbase = qr + ((size_t)bh * T_) * HD_;
    const __half* kbase = kr + ((size_t)(b*HKV_ + kvh) * T_) * HD_;
    const __half* vbase = vT + ((size_t)(b*HKV_ + kvh) * HD_) * T_;

    fa_issue(kbase, vbase, sbase, 0, 0, tid);

    // per-lane ldmatrix offsets
    int lrow = lane & 15, lcol = (lane >> 4) << 3;
    uint32_t kfoff = (uint32_t)((lrow*FK_STR + lcol)*2);
    uint32_t vfoff = (uint32_t)((lrow*FV_STR + lcol)*2);

    // preload Q fragments (warp rows wm..wm+15): 8 ksteps x 4 regs
    int wm = wid << 4;
    uint32_t qf[8][4];
    {
        const __half* r0p = qbase + (size_t)(q0 + wm + g)*HD_;
        const __half* r1p = qbase + (size_t)(q0 + wm + g + 8)*HD_;
#pragma unroll
        for (int ks = 0; ks < 8; ++ks) {
            int kk = (ks << 4) + (tig << 1);
            qf[ks][0] = __ldg((const uint32_t*)(r0p + kk));
            qf[ks][1] = __ldg((const uint32_t*)(r1p + kk));
            qf[ks][2] = __ldg((const uint32_t*)(r0p + kk + 8));
            qf[ks][3] = __ldg((const uint32_t*)(r1p + kk + 8));
        }
    }

    // o[0..15]: PV accumulators (d=128); o[16]: row-sum accumulator (ones-mma)
    float o[17][4];
#pragma unroll
    for (int nt = 0; nt < 17; ++nt)
#pragma unroll
        for (int r = 0; r < 4; ++r) o[nt][r] = 0.f;

    for (int kt = 0; kt < nkt; ++kt) {
        asm volatile("cp.async.wait_group 0;\n");
        __syncthreads();
        if (kt + 1 < nkt)
            fa_issue(kbase, vbase, sbase, (kt+1) & 1, (kt+1) << 7, tid);

        uint32_t ksb = sbase + ((kt & 1) ? FKS1 : FKS0)*2 + kfoff;
        uint32_t vtb = sbase + ((kt & 1) ? FVT1 : FVT0)*2 + vfoff;
        bool diag = (kt == nkt - 1);
        int k0t = kt << 7;
        int r0 = q0 + wm + g, r1 = r0 + 8;

        // ---- S + softmax, pair-by-pair (MUFU overlaps next pair's mma) ----
        uint32_t pf[8][4];
#pragma unroll
        for (int p = 0; p < 8; ++p) {
            float s0[4] = {0.f, 0.f, 0.f, 0.f};
            float s1[4] = {0.f, 0.f, 0.f, 0.f};
#pragma unroll
            for (int ks = 0; ks < 8; ++ks) {
                uint32_t b00, b01, b10, b11;
                ldsm4(b00, b01, b10, b11, ksb + (p << 5)*FK_STR + (ks << 5));
                mma_f16(s0, qf[ks], b00, b10);
                mma_f16(s1, qf[ks], b01, b11);
            }
            if (diag) {
                int c0 = k0t + (p << 4) + 2*tig,     c1 = c0 + 1;     // n-tile 2p
                int c2 = k0t + (p << 4) + 8 + 2*tig, c3 = c2 + 1;     // n-tile 2p+1
                if (c0 > r0) s0[0] = -1e30f;
                if (c1 > r0) s0[1] = -1e30f;
                if (c0 > r1) s0[2] = -1e30f;
                if (c1 > r1) s0[3] = -1e30f;
                if (c2 > r0) s1[0] = -1e30f;
                if (c3 > r0) s1[1] = -1e30f;
                if (c2 > r1) s1[2] = -1e30f;
                if (c3 > r1) s1[3] = -1e30f;
            }
            pf[p][0] = h2u(ex2f(s0[0] - SOFF), ex2f(s0[1] - SOFF));
            pf[p][1] = h2u(ex2f(s0[2] - SOFF), ex2f(s0[3] - SOFF));
            pf[p][2] = h2u(ex2f(s1[0] - SOFF), ex2f(s1[1] - SOFF));
            pf[p][3] = h2u(ex2f(s1[2] - SOFF), ex2f(s1[3] - SOFF));
        }

        // ---- O += P V ; l += P @ ones ----
#pragma unroll
        for (int ks2 = 0; ks2 < 8; ++ks2) {
#pragma unroll
            for (int p = 0; p < 8; ++p) {
                uint32_t b00, b01, b10, b11;
                ldsm4(b00, b01, b10, b11, vtb + (p << 5)*FV_STR + (ks2 << 5));
                mma_f16(o[2*p],     pf[ks2], b00, b10);
                mma_f16(o[2*p + 1], pf[ks2], b01, b11);
            }
            mma_f16(o[16], pf[ks2], ONE2, ONE2);
        }
    }

    // ---- epilogue: divide by l (from ones-mma), store fp16 ----
    float inv0 = 1.f / o[16][0], inv1 = 1.f / o[16][2];
    int gr0 = q0 + wm + g, gr1 = gr0 + 8;
    __half* ob0 = attn + ((size_t)(b*T_ + gr0))*D_ + h*HD_;
    __half* ob1 = attn + ((size_t)(b*T_ + gr1))*D_ + h*HD_;
#pragma unroll
    for (int nt = 0; nt < 16; ++nt) {
        int dcol = 8*nt + 2*tig;
        *(uint32_t*)(ob0 + dcol) = h2u(o[nt][0]*inv0, o[nt][1]*inv0);
        *(uint32_t*)(ob1 + dcol) = h2u(o[nt][2]*inv1, o[nt][3]*inv1);
    }
}

// ---------------- launch ----------------
extern "C" void kernel_launch(void* const* d_in, const int* in_sizes, int n_in,
                              void* d_out, int out_size) {
    const float* x  = (const float*)d_in[0];
    const float* Wq = (const float*)d_in[1];
    const float* Wk = (const float*)d_in[2];
    const float* Wv = (const float*)d_in[3];
    const float* Wo = (const float*)d_in[4];
    float* out = (float*)d_out;

    __half *xh, *wcatT, *worT, *qr, *kr, *vT, *attn;
    cudaGetSymbolAddress((void**)&xh,    g_xh);
    cudaGetSymbolAddress((void**)&wcatT, g_wcatT);
    cudaGetSymbolAddress((void**)&worT,  g_worT);
    cudaGetSymbolAddress((void**)&qr,    g_qr);
    cudaGetSymbolAddress((void**)&kr,    g_kr);
    cudaGetSymbolAddress((void**)&vT,    g_vT);
    cudaGetSymbolAddress((void**)&attn,  g_attn);

    rope_table_kernel<<<T_, 64>>>();

    // fused prep: x conversion + all weight transposes
    prep_all<<<18432, 256>>>((const float4*)x, (__half2*)xh, Wq, Wk, Wv, Wo, wcatT, worT);

    // fused QKV projection + RoPE + layout (writes qr/kr/vT directly)
    cudaFuncSetAttribute(gemm_qkv, cudaFuncAttributeMaxDynamicSharedMemorySize, GM_SMEM);
    gemm_qkv<<<dim3(NQKV/128, MROWS/128), 256, GM_SMEM>>>(xh, wcatT, qr, kr, vT);

    // fp16 flash attention (128-wide k tiles, f32-precise static-offset softmax)
    cudaFuncSetAttribute(flash_f16, cudaFuncAttributeMaxDynamicSharedMemorySize, FSM_BYTES);
    flash_f16<<<dim3(T_/128, B_*H_), 256, FSM_BYTES>>>(qr, kr, vT, attn);

    // output projection (f32 out)
    cudaFuncSetAttribute(gemm_f16, cudaFuncAttributeMaxDynamicSharedMemorySize, GM_SMEM);
    gemm_f16<<<dim3(D_/128, MROWS/128), 256, GM_SMEM>>>(attn, worT, out, D_, D_);
}

// round 16
// speedup vs baseline: 1.5234x; 1.5234x over previous
#include <cuda_runtime.h>
#include <cuda_fp16.h>
#include <math.h>
#include <stdint.h>

// ---------------- problem constants ----------------
#define B_   2
#define T_   2048
#define D_   2048
#define H_   16
#define HKV_ 4
#define HD_  128
#define DKV_ (HKV_*HD_)    // 512
#define NQKV 3072          // fused q|k|v projection width
#define MROWS (B_*T_)      // 4096
#define QSCALE ((float)(1.4426950408889634 * 0.08838834764831845))
#define SOFF  8.0f         // static softmax offset (log2 units); O/l ratio invariant

// ---------------- scratch (device globals) ----------------
__device__ __align__(16) __half g_xh   [(size_t)MROWS * D_];    // x in fp16
__device__ __align__(16) __half g_wcatT[(size_t)NQKV * D_];     // [Wq|Wk|Wv]^T fp16: [n][k]
__device__ __align__(16) __half g_worT [(size_t)D_ * D_];       // Wo^T fp16: [n][k]
__device__ __align__(16) __half g_qr   [(size_t)B_*H_*T_*HD_];  // Q roped, (bh,t,d)
__device__ __align__(16) __half g_kr   [(size_t)B_*HKV_*T_*HD_];// K roped
__device__ __align__(16) __half g_vT   [(size_t)B_*HKV_*HD_*T_];// V^T, (bkh,d,t)
__device__ __align__(16) __half g_attn [(size_t)MROWS * D_];    // attention out fp16
__device__ float g_cos_t[T_*64];
__device__ float g_sin_t[T_*64];

// ---------------- helpers ----------------
__device__ __forceinline__ uint32_t smem_u32(const void* p) {
    return (uint32_t)__cvta_generic_to_shared(p);
}
__device__ __forceinline__ void cp_async16(uint32_t dst, const void* src) {
    asm volatile("cp.async.cg.shared.global [%0], [%1], 16;\n" :: "r"(dst), "l"(src));
}
__device__ __forceinline__ void mma_f16(float* c, const uint32_t* a, uint32_t b0, uint32_t b1) {
    asm volatile(
        "mma.sync.aligned.m16n8k16.row.col.f32.f16.f16.f32 "
        "{%0,%1,%2,%3}, {%4,%5,%6,%7}, {%8,%9}, {%0,%1,%2,%3};\n"
        : "+f"(c[0]), "+f"(c[1]), "+f"(c[2]), "+f"(c[3])
        : "r"(a[0]), "r"(a[1]), "r"(a[2]), "r"(a[3]), "r"(b0), "r"(b1));
}
__device__ __forceinline__ void ldsm4(uint32_t& r0, uint32_t& r1, uint32_t& r2, uint32_t& r3,
                                      uint32_t addr) {
    asm volatile("ldmatrix.sync.aligned.m8n8.x4.shared.b16 {%0,%1,%2,%3}, [%4];"
        : "=r"(r0), "=r"(r1), "=r"(r2), "=r"(r3) : "r"(addr));
}
__device__ __forceinline__ uint32_t h2u(float a, float b) {
    __half2 h = __floats2half2_rn(a, b);
    return *(uint32_t*)&h;
}
__device__ __forceinline__ float ex2f(float x) {
    float r;
    asm("ex2.approx.f32 %0, %1;" : "=f"(r) : "f"(x));
    return r;
}

// ---------------- RoPE table (fp64 precompute) ----------------
__global__ void rope_table_kernel() {
    int t = blockIdx.x;
    int i = threadIdx.x;                       // 0..63
    double inv = exp(-((double)(2*i) / 128.0) * 9.210340371976182736);
    double ang = (double)t * inv;
    g_cos_t[t*64 + i] = (float)cos(ang);
    g_sin_t[t*64 + i] = (float)sin(ang);
}

// ---------------- f32 -> fp16 conversion ----------------
__global__ void conv_half(const float4* __restrict__ in, __half2* __restrict__ out, int n4) {
    int i = blockIdx.x * blockDim.x + threadIdx.x;
    if (i < n4) {
        float4 v = in[i];
        out[2*i]     = __floats2half2_rn(v.x, v.y);
        out[2*i + 1] = __floats2half2_rn(v.z, v.w);
    }
}

// ---------------- all 4 weight transposes in one launch ----------------
__global__ void trans_all(const float* __restrict__ Wq, const float* __restrict__ Wk,
                          const float* __restrict__ Wv, const float* __restrict__ Wo,
                          __half* __restrict__ wcatT, __half* __restrict__ worT) {
    __shared__ float S[32][33];
    int tile = blockIdx.x;
    const float* in;
    __half* out;
    int cols, n0, k0;
    if (tile < 4096)      { int t = tile;        in = Wq; out = wcatT;                   cols = D_;   n0 = (t & 63) << 5; k0 = (t >> 6) << 5; }
    else if (tile < 5120) { int t = tile - 4096; in = Wk; out = wcatT + (size_t)2048*D_; cols = DKV_; n0 = (t & 15) << 5; k0 = (t >> 4) << 5; }
    else if (tile < 6144) { int t = tile - 5120; in = Wv; out = wcatT + (size_t)2560*D_; cols = DKV_; n0 = (t & 15) << 5; k0 = (t >> 4) << 5; }
    else                  { int t = tile - 6144; in = Wo; out = worT;                    cols = D_;   n0 = (t & 63) << 5; k0 = (t >> 6) << 5; }
    for (int e = threadIdx.x; e < 1024; e += 256) {
        int r = e >> 5, c = e & 31;
        S[r][c] = in[(size_t)(k0 + r)*cols + n0 + c];
    }
    __syncthreads();
    for (int e = threadIdx.x; e < 1024; e += 256) {
        int r = e >> 5, c = e & 31;
        out[(size_t)(n0 + r)*D_ + k0 + c] = __float2half_rn(S[c][r]);
    }
}

// ---------------- GEMM: 128x128 CTA tile, BK=64, 3-stage ring, 1 barrier/iter ----------------
#define ASTR 72                                  // padded row stride (halfs), 144B: conflict-free
#define STG_HALFS (2*128*ASTR)                   // A tile + B tile per stage (18432)
#define GM_SMEM   (3*STG_HALFS*2)                // bytes (110592) -> 2 CTA/SM

__device__ __forceinline__ void gemm_issue(const __half* __restrict__ Ag,
                                           const __half* __restrict__ Bg,
                                           uint32_t sbase, int K, int tid) {
    uint32_t sB = sbase + 128*ASTR*2;
#pragma unroll
    for (int i = 0; i < 4; ++i) {                // A: 128 rows x 8 chunks of 16B
        int c = tid + (i << 8);
        int r = c >> 3, cb = (c & 7) << 3;
        cp_async16(sbase + (r*ASTR + cb)*2, Ag + (size_t)r*K + cb);
    }
#pragma unroll
    for (int i = 0; i < 4; ++i) {                // B: 128 rows x 8 chunks
        int c = tid + (i << 8);
        int r = c >> 3, cb = (c & 7) << 3;
        cp_async16(sB + (r*ASTR + cb)*2, Bg + (size_t)r*K + cb);
    }
    asm volatile("cp.async.commit_group;\n");
}

// mainloop shared by both GEMMs; declares acc[2][8][4]. BK=64, 4 ksteps/iter,
// single barrier per iter; ring of 3 stages, wait_group(1) keeps 1 load in flight.
#define GEMM_MAIN(A, Bt, K)                                                        \
    int lrow = lane & 15, lcol = (lane >> 4) << 3;                                 \
    uint32_t aoff[2], boff[4];                                                     \
    _Pragma("unroll")                                                              \
    for (int mt = 0; mt < 2; ++mt)                                                 \
        aoff[mt] = (uint32_t)(((wm + (mt << 4) + lrow)*ASTR + lcol)*2);            \
    _Pragma("unroll")                                                              \
    for (int p = 0; p < 4; ++p) {                                                  \
        int brow = bmap(p);                                                        \
        boff[p] = (uint32_t)(((128 + brow)*ASTR + lcol)*2);                        \
    }                                                                              \
    const __half* Abase = (A)  + (size_t)row0 * (K);                               \
    const __half* Bbase = (Bt) + (size_t)col0 * (K);                               \
    float acc[2][8][4];                                                            \
    _Pragma("unroll")                                                              \
    for (int mt = 0; mt < 2; ++mt)                                                 \
        _Pragma("unroll")                                                          \
        for (int nt = 0; nt < 8; ++nt)                                             \
            _Pragma("unroll")                                                      \
            for (int r = 0; r < 4; ++r) acc[mt][nt][r] = 0.f;                      \
    int iters = (K) / 64;                                                          \
    gemm_issue(Abase,      Bbase,      sbase,             (K), tid);               \
    gemm_issue(Abase + 64, Bbase + 64, sbase + STG_HALFS*2, (K), tid);             \
    for (int it = 0; it < iters; ++it) {                                           \
        if (it + 2 < iters) {                                                      \
            asm volatile("cp.async.wait_group %0;\n" :: "n"(1));                   \
        } else {                                                                   \
            asm volatile("cp.async.wait_group %0;\n" :: "n"(0));                   \
        }                                                                          \
        __syncthreads();                                                           \
        if (it + 2 < iters)                                                        \
            gemm_issue(Abase + (it+2)*64, Bbase + (it+2)*64,                       \
                       sbase + ((it+2) % 3)*STG_HALFS*2, (K), tid);                \
        uint32_t stg = sbase + (it % 3)*STG_HALFS*2;                               \
        _Pragma("unroll")                                                          \
        for (int ks = 0; ks < 4; ++ks) {                                           \
            uint32_t kb = stg + ks*32;                                             \
            uint32_t a[2][4], b[8][2];                                             \
            ldsm4(a[0][0], a[0][1], a[0][2], a[0][3], kb + aoff[0]);               \
            ldsm4(a[1][0], a[1][1], a[1][2], a[1][3], kb + aoff[1]);               \
            _Pragma("unroll")                                                      \
            for (int p = 0; p < 4; ++p)                                            \
                ldsm4(b[2*p][0], b[2*p+1][0], b[2*p][1], b[2*p+1][1], kb + boff[p]);\
            _Pragma("unroll")                                                      \
            for (int mt = 0; mt < 2; ++mt)                                         \
                _Pragma("unroll")                                                  \
                for (int nt = 0; nt < 8; ++nt)                                     \
                    mma_f16(acc[mt][nt], a[mt], b[nt][0], b[nt][1]);               \
        }                                                                          \
    }

// ---------------- Wo GEMM: C f32 = A @ Bt^T ----------------
__global__ __launch_bounds__(256, 2)
void gemm_f16(const __half* __restrict__ A, const __half* __restrict__ Bt,
              float* __restrict__ C, int K, int ldc) {
    extern __shared__ __half smh[];
    uint32_t sbase = smem_u32(smh);
    int tid  = threadIdx.x;
    int lane = tid & 31, wid = tid >> 5;
    int g = lane >> 2, tig = lane & 3;
    int wm = (wid >> 1) << 5;
    int wn = (wid & 1) << 6;
    int row0 = blockIdx.y << 7;
    int col0 = blockIdx.x << 7;

    #define bmap(p) (wn + ((p) << 4) + (lane & 15))
    GEMM_MAIN(A, Bt, K)
    #undef bmap

#pragma unroll
    for (int mt = 0; mt < 2; ++mt) {
#pragma unroll
        for (int nt = 0; nt < 8; ++nt) {
            int r    = row0 + wm + (mt << 4) + g;
            int ccol = col0 + wn + (nt << 3) + (tig << 1);
            *(float2*)(C + (size_t)r*ldc + ccol)       = make_float2(acc[mt][nt][0], acc[mt][nt][1]);
            *(float2*)(C + (size_t)(r + 8)*ldc + ccol) = make_float2(acc[mt][nt][2], acc[mt][nt][3]);
        }
    }
}

// ---------------- QKV GEMM with fused RoPE/layout epilogue ----------------
__global__ __launch_bounds__(256, 2)
void gemm_qkv(const __half* __restrict__ A, const __half* __restrict__ Bt,
              __half* __restrict__ qrOut, __half* __restrict__ krOut,
              __half* __restrict__ vtOut) {
    extern __shared__ __half smh[];
    uint32_t sbase = smem_u32(smh);
    int tid  = threadIdx.x;
    int lane = tid & 31, wid = tid >> 5;
    int g = lane >> 2, tig = lane & 3;
    int wm = (wid >> 1) << 5;
    int wn8 = (wid & 1) << 3;
    int row0 = blockIdx.y << 7;
    int col0 = blockIdx.x << 7;

    #define bmap(p) (wn8 + ((p) << 5) + ((lane & 8) << 1) + (lane & 7))
    GEMM_MAIN(A, Bt, D_)
    #undef bmap

    // -------- fused epilogue --------
    int head  = blockIdx.x;             // tile width 128 == one head
    int trow0 = row0 & (T_ - 1);
    int bb    = row0 >> 11;

    if (head < 20) {
        float scale = (head < 16) ? QSCALE : 1.0f;
        __half* obase = (head < 16)
            ? qrOut + ((size_t)(bb*H_   + head     )*T_ + trow0)*HD_
            : krOut + ((size_t)(bb*HKV_ + head - 16)*T_ + trow0)*HD_;
#pragma unroll
        for (int mt = 0; mt < 2; ++mt) {
#pragma unroll
            for (int rh = 0; rh < 2; ++rh) {
                int r = wm + (mt << 4) + g + (rh << 3);
                int t = trow0 + r;
                int i0 = rh << 1;
#pragma unroll
                for (int nt = 0; nt < 4; ++nt) {
                    int dm = wn8 + (nt << 4) + (tig << 1);
                    float2 cv = *(const float2*)&g_cos_t[t*64 + dm];
                    float2 sv = *(const float2*)&g_sin_t[t*64 + dm];
                    float a0 = acc[mt][nt][i0],     a1 = acc[mt][nt][i0+1];
                    float b0 = acc[mt][nt+4][i0],   b1 = acc[mt][nt+4][i0+1];
                    uint32_t lo = h2u((a0*cv.x - b0*sv.x)*scale,
                                      (a1*cv.y - b1*sv.y)*scale);
                    uint32_t hi = h2u((b0*cv.x + a0*sv.x)*scale,
                                      (b1*cv.y + a1*sv.y)*scale);
                    *(uint32_t*)&obase[(size_t)r*HD_ + dm]      = lo;
                    *(uint32_t*)&obase[(size_t)r*HD_ + dm + 64] = hi;
                }
            }
        }
    } else {
        // V: transpose through smem, write (bkh, d, t)
        __syncthreads();
        __half* S2 = smh;
#pragma unroll
        for (int mt = 0; mt < 2; ++mt)
#pragma unroll
            for (int nt = 0; nt < 8; ++nt) {
                int r = wm + (mt << 4) + g;
                int c = wn8 + (nt << 4) + (tig << 1);
                S2[(c    )*132 + r    ] = __float2half_rn(acc[mt][nt][0]);
                S2[(c + 1)*132 + r    ] = __float2half_rn(acc[mt][nt][1]);
                S2[(c    )*132 + r + 8] = __float2half_rn(acc[mt][nt][2]);
                S2[(c + 1)*132 + r + 8] = __float2half_rn(acc[mt][nt][3]);
            }
        __syncthreads();
        __half* obase = vtOut + ((size_t)(bb*HKV_ + head - 20)*HD_)*T_ + trow0;
#pragma unroll
        for (int d = wid; d < 128; d += 8) {
            uint32_t w0 = *(uint32_t*)&S2[d*132 + 2*lane];
            uint32_t w1 = *(uint32_t*)&S2[d*132 + 64 + 2*lane];
            *(uint32_t*)&obase[(size_t)d*T_ + 2*lane]      = w0;
            *(uint32_t*)&obase[(size_t)d*T_ + 64 + 2*lane] = w1;
        }
    }
}

// ---------------- flash attention: 128-wide k-tiles, static-offset softmax ----------------
// ks-outer S-phase (16 independent accumulator chains); ex2/pack of PV-kstep ks2
// computed just-in-time inside the PV loop so MUFU overlaps the previous kstep's
// tensor chain. P = exp2(s - SOFF) with f32 argument; l via ones-mma.
#define FK_STR 136
#define FV_STR 136
#define FKS0 0
#define FKS1 (128*FK_STR)                  // 17408
#define FVT0 (2*128*FK_STR)                // 34816
#define FVT1 (FVT0 + 128*FV_STR)           // 52224
#define FSM_BYTES ((FVT1 + 128*FV_STR)*2)  // 139264
#define ONE2 0x3C003C00u                   // half2(1.0, 1.0)

__device__ __forceinline__ void fa_issue(const __half* __restrict__ kbase,
                                         const __half* __restrict__ vbase,
                                         uint32_t sbase, int buf, int k0, int tid) {
    uint32_t ks = sbase + (buf ? FKS1 : FKS0)*2;
    uint32_t vt = sbase + (buf ? FVT1 : FVT0)*2;
#pragma unroll
    for (int i = 0; i < 8; ++i) {                 // K: 128 rows x 16 chunks
        int c = tid + (i << 8);
        int row = c >> 4, cb = (c & 15) << 3;
        cp_async16(ks + (row*FK_STR + cb)*2, kbase + (size_t)(k0 + row)*HD_ + cb);
    }
#pragma unroll
    for (int i = 0; i < 8; ++i) {                 // V^T: 128 d-rows x 16 t-chunks
        int c = tid + (i << 8);
        int d = c >> 4, cb = (c & 15) << 3;
        cp_async16(vt + (d*FV_STR + cb)*2, vbase + (size_t)d*T_ + k0 + cb);
    }
    asm volatile("cp.async.commit_group;\n");
}

__global__ __launch_bounds__(256, 1)
void flash_f16(const __half* __restrict__ qr, const __half* __restrict__ kr,
               const __half* __restrict__ vT, __half* __restrict__ attn) {
    extern __shared__ __half smh[];
    uint32_t sbase = smem_u32(smh);

    int tid = threadIdx.x, lane = tid & 31, wid = tid >> 5;
    int g = lane >> 2, tig = lane & 3;
    int qi = gridDim.x - 1 - blockIdx.x;          // heavy tiles first
    int q0 = qi << 7;
    int bh = blockIdx.y;
    int b = bh >> 4, h = bh & 15, kvh = h >> 2;
    int nkt = qi + 1;                             // 128-wide k tiles

    const __half* qbase = qr + ((size_t)bh * T_) * HD_;
    const __half* kbase = kr + ((size_t)(b*HKV_ + kvh) * T_) * HD_;
    const __half* vbase = vT + ((size_t)(b*HKV_ + kvh) * HD_) * T_;

    fa_issue(kbase, vbase, sbase, 0, 0, tid);

    // per-lane ldmatrix offsets
    int lrow = lane & 15, lcol = (lane >> 4) << 3;
    uint32_t kfoff = (uint32_t)((lrow*FK_STR + lcol)*2);
    uint32_t vfoff = (uint32_t)((lrow*FV_STR + lcol)*2);

    // preload Q fragments (warp rows wm..wm+15): 8 ksteps x 4 regs
    int wm = wid << 4;
    uint32_t qf[8][4];
    {
        const __half* r0p = qbase + (size_t)(q0 + wm + g)*HD_;
        const __half* r1p = qbase + (size_t)(q0 + wm + g + 8)*HD_;
#pragma unroll
        for (int ks = 0; ks < 8; ++ks) {
            int kk = (ks << 4) + (tig << 1);
            qf[ks][0] = __ldg((const uint32_t*)(r0p + kk));
            qf[ks][1] = __ldg((const uint32_t*)(r1p + kk));
            qf[ks][2] = __ldg((const uint32_t*)(r0p + kk + 8));
            qf[ks][3] = __ldg((const uint32_t*)(r1p + kk + 8));
        }
    }

    // o[0..15]: PV accumulators (d=128); o[16]: row-sum accumulator (ones-mma)
    float o[17][4];
#pragma unroll
    for (int nt = 0; nt < 17; ++nt)
#pragma unroll
        for (int r = 0; r < 4; ++r) o[nt][r] = 0.f;

    for (int kt = 0; kt < nkt; ++kt) {
        asm volatile("cp.async.wait_group 0;\n");
        __syncthreads();
        if (kt + 1 < nkt)
            fa_issue(kbase, vbase, sbase, (kt+1) & 1, (kt+1) << 7, tid);

        uint32_t ksb = sbase + ((kt & 1) ? FKS1 : FKS0)*2 + kfoff;
        uint32_t vtb = sbase + ((kt & 1) ? FVT1 : FVT0)*2 + vfoff;

        // ---- S = Q K^T over 128 k-cols (16 n-tiles, ks-outer: max ILP) ----
        float sacc[16][4];
#pragma unroll
        for (int nt = 0; nt < 16; ++nt)
#pragma unroll
            for (int r = 0; r < 4; ++r) sacc[nt][r] = 0.f;
#pragma unroll
        for (int ks = 0; ks < 8; ++ks) {
#pragma unroll
            for (int p = 0; p < 8; ++p) {
                uint32_t b00, b01, b10, b11;
                ldsm4(b00, b01, b10, b11, ksb + (p << 5)*FK_STR + (ks << 5));
                mma_f16(sacc[2*p],     qf[ks], b00, b10);
                mma_f16(sacc[2*p + 1], qf[ks], b01, b11);
            }
        }

        // ---- causal mask on the diagonal k-tile (kt == nkt-1, k0 == q0) ----
        if (kt == nkt - 1) {
            int k0 = kt << 7;
            int r0 = q0 + wm + g, r1 = r0 + 8;
#pragma unroll
            for (int nt = 0; nt < 16; ++nt) {
                int c0 = k0 + 8*nt + 2*tig, c1 = c0 + 1;
                if (c0 > r0) sacc[nt][0] = -1e30f;
                if (c1 > r0) sacc[nt][1] = -1e30f;
                if (c0 > r1) sacc[nt][2] = -1e30f;
                if (c1 > r1) sacc[nt][3] = -1e30f;
            }
        }

        // ---- PV loop with just-in-time ex2/pack: MUFU(ks2) overlaps mma(ks2-1) ----
#pragma unroll
        for (int ks2 = 0; ks2 < 8; ++ks2) {
            uint32_t pf[4];
            pf[0] = h2u(ex2f(sacc[2*ks2    ][0] - SOFF), ex2f(sacc[2*ks2    ][1] - SOFF));
            pf[1] = h2u(ex2f(sacc[2*ks2    ][2] - SOFF), ex2f(sacc[2*ks2    ][3] - SOFF));
            pf[2] = h2u(ex2f(sacc[2*ks2 + 1][0] - SOFF), ex2f(sacc[2*ks2 + 1][1] - SOFF));
            pf[3] = h2u(ex2f(sacc[2*ks2 + 1][2] - SOFF), ex2f(sacc[2*ks2 + 1][3] - SOFF));
#pragma unroll
            for (int p = 0; p < 8; ++p) {
                uint32_t b00, b01, b10, b11;
                ldsm4(b00, b01, b10, b11, vtb + (p << 5)*FV_STR + (ks2 << 5));
                mma_f16(o[2*p],     pf, b00, b10);
                mma_f16(o[2*p + 1], pf, b01, b11);
            }
            mma_f16(o[16], pf, ONE2, ONE2);
        }
    }

    // ---- epilogue: divide by l (from ones-mma), store fp16 ----
    float inv0 = 1.f / o[16][0], inv1 = 1.f / o[16][2];
    int gr0 = q0 + wm + g, gr1 = gr0 + 8;
    __half* ob0 = attn + ((size_t)(b*T_ + gr0))*D_ + h*HD_;
    __half* ob1 = attn + ((size_t)(b*T_ + gr1))*D_ + h*HD_;
#pragma unroll
    for (int nt = 0; nt < 16; ++nt) {
        int dcol = 8*nt + 2*tig;
        *(uint32_t*)(ob0 + dcol) = h2u(o[nt][0]*inv0, o[nt][1]*inv0);
        *(uint32_t*)(ob1 + dcol) = h2u(o[nt][2]*inv1, o[nt][3]*inv1);
    }
}

// ---------------- launch ----------------
extern "C" void kernel_launch(void* const* d_in, const int* in_sizes, int n_in,
                              void* d_out, int out_size) {
    const float* x  = (const float*)d_in[0];
    const float* Wq = (const float*)d_in[1];
    const float* Wk = (const float*)d_in[2];
    const float* Wv = (const float*)d_in[3];
    const float* Wo = (const float*)d_in[4];
    float* out = (float*)d_out;

    __half *xh, *wcatT, *worT, *qr, *kr, *vT, *attn;
    cudaGetSymbolAddress((void**)&xh,    g_xh);
    cudaGetSymbolAddress((void**)&wcatT, g_wcatT);
    cudaGetSymbolAddress((void**)&worT,  g_worT);
    cudaGetSymbolAddress((void**)&qr,    g_qr);
    cudaGetSymbolAddress((void**)&kr,    g_kr);
    cudaGetSymbolAddress((void**)&vT,    g_vT);
    cudaGetSymbolAddress((void**)&attn,  g_attn);

    rope_table_kernel<<<T_, 64>>>();

    // fp16 conversion of x; all weight transposes in one launch
    int n4x = MROWS*D_/4;
    conv_half<<<(n4x + 255)/256, 256>>>((const float4*)x, (__half2*)xh, n4x);
    trans_all<<<10240, 256>>>(Wq, Wk, Wv, Wo, wcatT, worT);

    // fused QKV projection + RoPE + layout (writes qr/kr/vT directly)
    cudaFuncSetAttribute(gemm_qkv, cudaFuncAttributeMaxDynamicSharedMemorySize, GM_SMEM);
    gemm_qkv<<<dim3(NQKV/128, MROWS/128), 256, GM_SMEM>>>(xh, wcatT, qr, kr, vT);

    // fp16 flash attention (128-wide k tiles, JIT ex2 in PV loop)
    cudaFuncSetAttribute(flash_f16, cudaFuncAttributeMaxDynamicSharedMemorySize, FSM_BYTES);
    flash_f16<<<dim3(T_/128, B_*H_), 256, FSM_BYTES>>>(qr, kr, vT, attn);

    // output projection (f32 out)
    cudaFuncSetAttribute(gemm_f16, cudaFuncAttributeMaxDynamicSharedMemorySize, GM_SMEM);
    gemm_f16<<<dim3(D_/128, MROWS/128), 256, GM_SMEM>>>(attn, worT, out, D_, D_);
}

// round 17
// speedup vs baseline: 1.6182x; 1.0622x over previous
#include <cuda_runtime.h>
#include <cuda_fp16.h>
#include <math.h>
#include <stdint.h>

// ---------------- problem constants ----------------
#define B_   2
#define T_   2048
#define D_   2048
#define H_   16
#define HKV_ 4
#define HD_  128
#define DKV_ (HKV_*HD_)    // 512
#define NQKV 3072          // fused q|k|v projection width
#define MROWS (B_*T_)      // 4096
#define QSCALE ((float)(1.4426950408889634 * 0.08838834764831845))
#define SOFF  8.0f         // static softmax offset (log2 units); O/l ratio invariant
#define NSM    148
#define NITEMS 512         // 16 q-tiles x 32 (b,h)

// ---------------- scratch (device globals) ----------------
__device__ __align__(16) __half g_xh   [(size_t)MROWS * D_];    // x in fp16
__device__ __align__(16) __half g_wcatT[(size_t)NQKV * D_];     // [Wq|Wk|Wv]^T fp16: [n][k]
__device__ __align__(16) __half g_worT [(size_t)D_ * D_];       // Wo^T fp16: [n][k]
__device__ __align__(16) __half g_qr   [(size_t)B_*H_*T_*HD_];  // Q roped, (bh,t,d)
__device__ __align__(16) __half g_kr   [(size_t)B_*HKV_*T_*HD_];// K roped
__device__ __align__(16) __half g_vT   [(size_t)B_*HKV_*HD_*T_];// V^T, (bkh,d,t)
__device__ __align__(16) __half g_attn [(size_t)MROWS * D_];    // attention out fp16
__device__ float g_cos_t[T_*64];
__device__ float g_sin_t[T_*64];

// ---------------- helpers ----------------
__device__ __forceinline__ uint32_t smem_u32(const void* p) {
    return (uint32_t)__cvta_generic_to_shared(p);
}
__device__ __forceinline__ void cp_async16(uint32_t dst, const void* src) {
    asm volatile("cp.async.cg.shared.global [%0], [%1], 16;\n" :: "r"(dst), "l"(src));
}
__device__ __forceinline__ void mma_f16(float* c, const uint32_t* a, uint32_t b0, uint32_t b1) {
    asm volatile(
        "mma.sync.aligned.m16n8k16.row.col.f32.f16.f16.f32 "
        "{%0,%1,%2,%3}, {%4,%5,%6,%7}, {%8,%9}, {%0,%1,%2,%3};\n"
        : "+f"(c[0]), "+f"(c[1]), "+f"(c[2]), "+f"(c[3])
        : "r"(a[0]), "r"(a[1]), "r"(a[2]), "r"(a[3]), "r"(b0), "r"(b1));
}
__device__ __forceinline__ void ldsm4(uint32_t& r0, uint32_t& r1, uint32_t& r2, uint32_t& r3,
                                      uint32_t addr) {
    asm volatile("ldmatrix.sync.aligned.m8n8.x4.shared.b16 {%0,%1,%2,%3}, [%4];"
        : "=r"(r0), "=r"(r1), "=r"(r2), "=r"(r3) : "r"(addr));
}
__device__ __forceinline__ uint32_t h2u(float a, float b) {
    __half2 h = __floats2half2_rn(a, b);
    return *(uint32_t*)&h;
}
__device__ __forceinline__ float ex2f(float x) {
    float r;
    asm("ex2.approx.f32 %0, %1;" : "=f"(r) : "f"(x));
    return r;
}

// ---------------- RoPE table (fp64 precompute) ----------------
__global__ void rope_table_kernel() {
    int t = blockIdx.x;
    int i = threadIdx.x;                       // 0..63
    double inv = exp(-((double)(2*i) / 128.0) * 9.210340371976182736);
    double ang = (double)t * inv;
    g_cos_t[t*64 + i] = (float)cos(ang);
    g_sin_t[t*64 + i] = (float)sin(ang);
}

// ---------------- f32 -> fp16 conversion ----------------
__global__ void conv_half(const float4* __restrict__ in, __half2* __restrict__ out, int n4) {
    int i = blockIdx.x * blockDim.x + threadIdx.x;
    if (i < n4) {
        float4 v = in[i];
        out[2*i]     = __floats2half2_rn(v.x, v.y);
        out[2*i + 1] = __floats2half2_rn(v.z, v.w);
    }
}

// ---------------- all 4 weight transposes in one launch ----------------
__global__ void trans_all(const float* __restrict__ Wq, const float* __restrict__ Wk,
                          const float* __restrict__ Wv, const float* __restrict__ Wo,
                          __half* __restrict__ wcatT, __half* __restrict__ worT) {
    __shared__ float S[32][33];
    int tile = blockIdx.x;
    const float* in;
    __half* out;
    int cols, n0, k0;
    if (tile < 4096)      { int t = tile;        in = Wq; out = wcatT;                   cols = D_;   n0 = (t & 63) << 5; k0 = (t >> 6) << 5; }
    else if (tile < 5120) { int t = tile - 4096; in = Wk; out = wcatT + (size_t)2048*D_; cols = DKV_; n0 = (t & 15) << 5; k0 = (t >> 4) << 5; }
    else if (tile < 6144) { int t = tile - 5120; in = Wv; out = wcatT + (size_t)2560*D_; cols = DKV_; n0 = (t & 15) << 5; k0 = (t >> 4) << 5; }
    else                  { int t = tile - 6144; in = Wo; out = worT;                    cols = D_;   n0 = (t & 63) << 5; k0 = (t >> 6) << 5; }
    for (int e = threadIdx.x; e < 1024; e += 256) {
        int r = e >> 5, c = e & 31;
        S[r][c] = in[(size_t)(k0 + r)*cols + n0 + c];
    }
    __syncthreads();
    for (int e = threadIdx.x; e < 1024; e += 256) {
        int r = e >> 5, c = e & 31;
        out[(size_t)(n0 + r)*D_ + k0 + c] = __float2half_rn(S[c][r]);
    }
}

// ---------------- GEMM: 128x128 CTA tile, BK=64, 3-stage ring, 1 barrier/iter ----------------
#define ASTR 72                                  // padded row stride (halfs), 144B: conflict-free
#define STG_HALFS (2*128*ASTR)                   // A tile + B tile per stage (18432)
#define GM_SMEM   (3*STG_HALFS*2)                // bytes (110592) -> 2 CTA/SM

__device__ __forceinline__ void gemm_issue(const __half* __restrict__ Ag,
                                           const __half* __restrict__ Bg,
                                           uint32_t sbase, int K, int tid) {
    uint32_t sB = sbase + 128*ASTR*2;
#pragma unroll
    for (int i = 0; i < 4; ++i) {                // A: 128 rows x 8 chunks of 16B
        int c = tid + (i << 8);
        int r = c >> 3, cb = (c & 7) << 3;
        cp_async16(sbase + (r*ASTR + cb)*2, Ag + (size_t)r*K + cb);
    }
#pragma unroll
    for (int i = 0; i < 4; ++i) {                // B: 128 rows x 8 chunks
        int c = tid + (i << 8);
        int r = c >> 3, cb = (c & 7) << 3;
        cp_async16(sB + (r*ASTR + cb)*2, Bg + (size_t)r*K + cb);
    }
    asm volatile("cp.async.commit_group;\n");
}

// mainloop shared by both GEMMs; declares acc[2][8][4]. BK=64, 4 ksteps/iter,
// single barrier per iter; ring of 3 stages, wait_group(1) keeps 1 load in flight.
#define GEMM_MAIN(A, Bt, K)                                                        \
    int lrow = lane & 15, lcol = (lane >> 4) << 3;                                 \
    uint32_t aoff[2], boff[4];                                                     \
    _Pragma("unroll")                                                              \
    for (int mt = 0; mt < 2; ++mt)                                                 \
        aoff[mt] = (uint32_t)(((wm + (mt << 4) + lrow)*ASTR + lcol)*2);            \
    _Pragma("unroll")                                                              \
    for (int p = 0; p < 4; ++p) {                                                  \
        int brow = bmap(p);                                                        \
        boff[p] = (uint32_t)(((128 + brow)*ASTR + lcol)*2);                        \
    }                                                                              \
    const __half* Abase = (A)  + (size_t)row0 * (K);                               \
    const __half* Bbase = (Bt) + (size_t)col0 * (K);                               \
    float acc[2][8][4];                                                            \
    _Pragma("unroll")                                                              \
    for (int mt = 0; mt < 2; ++mt)                                                 \
        _Pragma("unroll")                                                          \
        for (int nt = 0; nt < 8; ++nt)                                             \
            _Pragma("unroll")                                                      \
            for (int r = 0; r < 4; ++r) acc[mt][nt][r] = 0.f;                      \
    int iters = (K) / 64;                                                          \
    gemm_issue(Abase,      Bbase,      sbase,             (K), tid);               \
    gemm_issue(Abase + 64, Bbase + 64, sbase + STG_HALFS*2, (K), tid);             \
    for (int it = 0; it < iters; ++it) {                                           \
        if (it + 2 < iters) {                                                      \
            asm volatile("cp.async.wait_group %0;\n" :: "n"(1));                   \
        } else {                                                                   \
            asm volatile("cp.async.wait_group %0;\n" :: "n"(0));                   \
        }                                                                          \
        __syncthreads();                                                           \
        if (it + 2 < iters)                                                        \
            gemm_issue(Abase + (it+2)*64, Bbase + (it+2)*64,                       \
                       sbase + ((it+2) % 3)*STG_HALFS*2, (K), tid);                \
        uint32_t stg = sbase + (it % 3)*STG_HALFS*2;                               \
        _Pragma("unroll")                                                          \
        for (int ks = 0; ks < 4; ++ks) {                                           \
            uint32_t kb = stg + ks*32;                                             \
            uint32_t a[2][4], b[8][2];                                             \
            ldsm4(a[0][0], a[0][1], a[0][2], a[0][3], kb + aoff[0]);               \
            ldsm4(a[1][0], a[1][1], a[1][2], a[1][3], kb + aoff[1]);               \
            _Pragma("unroll")                                                      \
            for (int p = 0; p < 4; ++p)                                            \
                ldsm4(b[2*p][0], b[2*p+1][0], b[2*p][1], b[2*p+1][1], kb + boff[p]);\
            _Pragma("unroll")                                                      \
            for (int mt = 0; mt < 2; ++mt)                                         \
                _Pragma("unroll")                                                  \
                for (int nt = 0; nt < 8; ++nt)                                     \
                    mma_f16(acc[mt][nt], a[mt], b[nt][0], b[nt][1]);               \
        }                                                                          \
    }

// ---------------- Wo GEMM: C f32 = A @ Bt^T ----------------
__global__ __launch_bounds__(256, 2)
void gemm_f16(const __half* __restrict__ A, const __half* __restrict__ Bt,
              float* __restrict__ C, int K, int ldc) {
    extern __shared__ __half smh[];
    uint32_t sbase = smem_u32(smh);
    int tid  = threadIdx.x;
    int lane = tid & 31, wid = tid >> 5;
    int g = lane >> 2, tig = lane & 3;
    int wm = (wid >> 1) << 5;
    int wn = (wid & 1) << 6;
    int row0 = blockIdx.y << 7;
    int col0 = blockIdx.x << 7;

    #define bmap(p) (wn + ((p) << 4) + (lane & 15))
    GEMM_MAIN(A, Bt, K)
    #undef bmap

#pragma unroll
    for (int mt = 0; mt < 2; ++mt) {
#pragma unroll
        for (int nt = 0; nt < 8; ++nt) {
            int r    = row0 + wm + (mt << 4) + g;
            int ccol = col0 + wn + (nt << 3) + (tig << 1);
            *(float2*)(C + (size_t)r*ldc + ccol)       = make_float2(acc[mt][nt][0], acc[mt][nt][1]);
            *(float2*)(C + (size_t)(r + 8)*ldc + ccol) = make_float2(acc[mt][nt][2], acc[mt][nt][3]);
        }
    }
}

// ---------------- QKV GEMM with fused RoPE/layout epilogue ----------------
__global__ __launch_bounds__(256, 2)
void gemm_qkv(const __half* __restrict__ A, const __half* __restrict__ Bt,
              __half* __restrict__ qrOut, __half* __restrict__ krOut,
              __half* __restrict__ vtOut) {
    extern __shared__ __half smh[];
    uint32_t sbase = smem_u32(smh);
    int tid  = threadIdx.x;
    int lane = tid & 31, wid = tid >> 5;
    int g = lane >> 2, tig = lane & 3;
    int wm = (wid >> 1) << 5;
    int wn8 = (wid & 1) << 3;
    int row0 = blockIdx.y << 7;
    int col0 = blockIdx.x << 7;

    #define bmap(p) (wn8 + ((p) << 5) + ((lane & 8) << 1) + (lane & 7))
    GEMM_MAIN(A, Bt, D_)
    #undef bmap

    // -------- fused epilogue --------
    int head  = blockIdx.x;             // tile width 128 == one head
    int trow0 = row0 & (T_ - 1);
    int bb    = row0 >> 11;

    if (head < 20) {
        float scale = (head < 16) ? QSCALE : 1.0f;
        __half* obase = (head < 16)
            ? qrOut + ((size_t)(bb*H_   + head     )*T_ + trow0)*HD_
            : krOut + ((size_t)(bb*HKV_ + head - 16)*T_ + trow0)*HD_;
#pragma unroll
        for (int mt = 0; mt < 2; ++mt) {
#pragma unroll
            for (int rh = 0; rh < 2; ++rh) {
                int r = wm + (mt << 4) + g + (rh << 3);
                int t = trow0 + r;
                int i0 = rh << 1;
#pragma unroll
                for (int nt = 0; nt < 4; ++nt) {
                    int dm = wn8 + (nt << 4) + (tig << 1);
                    float2 cv = *(const float2*)&g_cos_t[t*64 + dm];
                    float2 sv = *(const float2*)&g_sin_t[t*64 + dm];
                    float a0 = acc[mt][nt][i0],     a1 = acc[mt][nt][i0+1];
                    float b0 = acc[mt][nt+4][i0],   b1 = acc[mt][nt+4][i0+1];
                    uint32_t lo = h2u((a0*cv.x - b0*sv.x)*scale,
                                      (a1*cv.y - b1*sv.y)*scale);
                    uint32_t hi = h2u((b0*cv.x + a0*sv.x)*scale,
                                      (b1*cv.y + a1*sv.y)*scale);
                    *(uint32_t*)&obase[(size_t)r*HD_ + dm]      = lo;
                    *(uint32_t*)&obase[(size_t)r*HD_ + dm + 64] = hi;
                }
            }
        }
    } else {
        // V: transpose through smem, write (bkh, d, t)
        __syncthreads();
        __half* S2 = smh;
#pragma unroll
        for (int mt = 0; mt < 2; ++mt)
#pragma unroll
            for (int nt = 0; nt < 8; ++nt) {
                int r = wm + (mt << 4) + g;
                int c = wn8 + (nt << 4) + (tig << 1);
                S2[(c    )*132 + r    ] = __float2half_rn(acc[mt][nt][0]);
                S2[(c + 1)*132 + r    ] = __float2half_rn(acc[mt][nt][1]);
                S2[(c    )*132 + r + 8] = __float2half_rn(acc[mt][nt][2]);
                S2[(c + 1)*132 + r + 8] = __float2half_rn(acc[mt][nt][3]);
            }
        __syncthreads();
        __half* obase = vtOut + ((size_t)(bb*HKV_ + head - 20)*HD_)*T_ + trow0;
#pragma unroll
        for (int d = wid; d < 128; d += 8) {
            uint32_t w0 = *(uint32_t*)&S2[d*132 + 2*lane];
            uint32_t w1 = *(uint32_t*)&S2[d*132 + 64 + 2*lane];
            *(uint32_t*)&obase[(size_t)d*T_ + 2*lane]      = w0;
            *(uint32_t*)&obase[(size_t)d*T_ + 64 + 2*lane] = w1;
        }
    }
}

// ---------------- persistent flash attention: snake work items, 128-wide k-tiles ----------------
// 148 CTAs loop over 512 (q-tile, head) items, heaviest first, snake-interleaved
// for balance. Double buffer carries ACROSS items: last k-tile of an item
// prefetches the next item's first K/V tile, hiding epilogue + Q preload.
#define FK_STR 136
#define FV_STR 136
#define FKS0 0
#define FKS1 (128*FK_STR)                  // 17408
#define FVT0 (2*128*FK_STR)                // 34816
#define FVT1 (FVT0 + 128*FV_STR)           // 52224
#define FSM_BYTES ((FVT1 + 128*FV_STR)*2)  // 139264
#define ONE2 0x3C003C00u                   // half2(1.0, 1.0)

__device__ __forceinline__ void fa_issue(const __half* __restrict__ kbase,
                                         const __half* __restrict__ vbase,
                                         uint32_t sbase, int buf, int k0, int tid) {
    uint32_t ks = sbase + (buf ? FKS1 : FKS0)*2;
    uint32_t vt = sbase + (buf ? FVT1 : FVT0)*2;
#pragma unroll
    for (int i = 0; i < 8; ++i) {                 // K: 128 rows x 16 chunks
        int c = tid + (i << 8);
        int row = c >> 4, cb = (c & 15) << 3;
        cp_async16(ks + (row*FK_STR + cb)*2, kbase + (size_t)(k0 + row)*HD_ + cb);
    }
#pragma unroll
    for (int i = 0; i < 8; ++i) {                 // V^T: 128 d-rows x 16 t-chunks
        int c = tid + (i << 8);
        int d = c >> 4, cb = (c & 15) << 3;
        cp_async16(vt + (d*FV_STR + cb)*2, vbase + (size_t)d*T_ + k0 + cb);
    }
    asm volatile("cp.async.commit_group;\n");
}

__global__ __launch_bounds__(256, 1)
void flash_f16(const __half* __restrict__ qr, const __half* __restrict__ kr,
               const __half* __restrict__ vT, __half* __restrict__ attn) {
    extern __shared__ __half smh[];
    uint32_t sbase = smem_u32(smh);

    int tid = threadIdx.x, lane = tid & 31, wid = tid >> 5;
    int g = lane >> 2, tig = lane & 3;
    int lrow = lane & 15, lcol = (lane >> 4) << 3;
    uint32_t kfoff = (uint32_t)((lrow*FK_STR + lcol)*2);
    uint32_t vfoff = (uint32_t)((lrow*FV_STR + lcol)*2);
    int wm = wid << 4;
    int cta = (int)blockIdx.x;

    // first work item (heavy-first: item/32 -> qi rank)
    int j = 0;
    int item = cta;
    int qi = 15 - (item >> 5);
    int bh = item & 31;
    int b = bh >> 4, h = bh & 15, kvh = h >> 2;
    int q0 = qi << 7, nkt = qi + 1;
    const __half* qb = qr + ((size_t)bh * T_) * HD_;
    const __half* kb = kr + ((size_t)(b*HKV_ + kvh) * T_) * HD_;
    const __half* vb = vT + ((size_t)(b*HKV_ + kvh) * HD_) * T_;

    int vbuf = 0;
    fa_issue(kb, vb, sbase, 0, 0, tid);

    while (true) {
        // per-item: preload Q fragments, zero accumulators
        uint32_t qf[8][4];
        {
            const __half* r0p = qb + (size_t)(q0 + wm + g)*HD_;
            const __half* r1p = qb + (size_t)(q0 + wm + g + 8)*HD_;
#pragma unroll
            for (int ks = 0; ks < 8; ++ks) {
                int kk = (ks << 4) + (tig << 1);
                qf[ks][0] = __ldg((const uint32_t*)(r0p + kk));
                qf[ks][1] = __ldg((const uint32_t*)(r1p + kk));
                qf[ks][2] = __ldg((const uint32_t*)(r0p + kk + 8));
                qf[ks][3] = __ldg((const uint32_t*)(r1p + kk + 8));
            }
        }
        float o[17][4];
#pragma unroll
        for (int nt = 0; nt < 17; ++nt)
#pragma unroll
            for (int r = 0; r < 4; ++r) o[nt][r] = 0.f;

        for (int kt = 0; kt < nkt; ++kt) {
            asm volatile("cp.async.wait_group 0;\n");
            __syncthreads();

            // prefetch next visit (same item, or next item's first tile)
            if (kt + 1 < nkt) {
                fa_issue(kb, vb, sbase, vbuf ^ 1, (kt+1) << 7, tid);
            } else {
                int nj = j + 1;
                int nitem = (nj & 1) ? (NSM*nj + (NSM-1) - cta) : (NSM*nj + cta);
                if (nitem < NITEMS) {
                    int nbh = nitem & 31;
                    int nb = nbh >> 4, nkvh = (nbh & 15) >> 2;
                    const __half* nkb = kr + ((size_t)(nb*HKV_ + nkvh) * T_) * HD_;
                    const __half* nvb = vT + ((size_t)(nb*HKV_ + nkvh) * HD_) * T_;
                    fa_issue(nkb, nvb, sbase, vbuf ^ 1, 0, tid);
                }
            }

            uint32_t ksb = sbase + (vbuf ? FKS1 : FKS0)*2 + kfoff;
            uint32_t vtb = sbase + (vbuf ? FVT1 : FVT0)*2 + vfoff;

            // ---- S = Q K^T over 128 k-cols (ks-outer: 16 independent chains) ----
            float sacc[16][4];
#pragma unroll
            for (int nt = 0; nt < 16; ++nt)
#pragma unroll
                for (int r = 0; r < 4; ++r) sacc[nt][r] = 0.f;
#pragma unroll
            for (int ks = 0; ks < 8; ++ks) {
#pragma unroll
                for (int p = 0; p < 8; ++p) {
                    uint32_t b00, b01, b10, b11;
                    ldsm4(b00, b01, b10, b11, ksb + (p << 5)*FK_STR + (ks << 5));
                    mma_f16(sacc[2*p],     qf[ks], b00, b10);
                    mma_f16(sacc[2*p + 1], qf[ks], b01, b11);
                }
            }

            // ---- causal mask on the diagonal k-tile ----
            if (kt == nkt - 1) {
                int k0 = kt << 7;
                int r0 = q0 + wm + g, r1 = r0 + 8;
#pragma unroll
                for (int nt = 0; nt < 16; ++nt) {
                    int c0 = k0 + 8*nt + 2*tig, c1 = c0 + 1;
                    if (c0 > r0) sacc[nt][0] = -1e30f;
                    if (c1 > r0) sacc[nt][1] = -1e30f;
                    if (c0 > r1) sacc[nt][2] = -1e30f;
                    if (c1 > r1) sacc[nt][3] = -1e30f;
                }
            }

            // ---- PV loop with JIT ex2 (f32 arg) ----
#pragma unroll
            for (int ks2 = 0; ks2 < 8; ++ks2) {
                uint32_t pf[4];
                pf[0] = h2u(ex2f(sacc[2*ks2    ][0] - SOFF), ex2f(sacc[2*ks2    ][1] - SOFF));
                pf[1] = h2u(ex2f(sacc[2*ks2    ][2] - SOFF), ex2f(sacc[2*ks2    ][3] - SOFF));
                pf[2] = h2u(ex2f(sacc[2*ks2 + 1][0] - SOFF), ex2f(sacc[2*ks2 + 1][1] - SOFF));
                pf[3] = h2u(ex2f(sacc[2*ks2 + 1][2] - SOFF), ex2f(sacc[2*ks2 + 1][3] - SOFF));
#pragma unroll
                for (int p = 0; p < 8; ++p) {
                    uint32_t b00, b01, b10, b11;
                    ldsm4(b00, b01, b10, b11, vtb + (p << 5)*FV_STR + (ks2 << 5));
                    mma_f16(o[2*p],     pf, b00, b10);
                    mma_f16(o[2*p + 1], pf, b01, b11);
                }
                mma_f16(o[16], pf, ONE2, ONE2);
            }
            vbuf ^= 1;
        }

        // ---- epilogue: divide by l (ones-mma), store fp16 ----
        {
            float inv0 = 1.f / o[16][0], inv1 = 1.f / o[16][2];
            int gr0 = q0 + wm + g, gr1 = gr0 + 8;
            __half* ob0 = attn + ((size_t)(b*T_ + gr0))*D_ + h*HD_;
            __half* ob1 = attn + ((size_t)(b*T_ + gr1))*D_ + h*HD_;
#pragma unroll
            for (int nt = 0; nt < 16; ++nt) {
                int dcol = 8*nt + 2*tig;
                *(uint32_t*)(ob0 + dcol) = h2u(o[nt][0]*inv0, o[nt][1]*inv0);
                *(uint32_t*)(ob1 + dcol) = h2u(o[nt][2]*inv1, o[nt][3]*inv1);
            }
        }

        // ---- advance to next snake item ----
        ++j;
        item = (j & 1) ? (NSM*j + (NSM-1) - cta) : (NSM*j + cta);
        if (item >= NITEMS) break;
        qi = 15 - (item >> 5);
        bh = item & 31;
        b = bh >> 4; h = bh & 15; kvh = h >> 2;
        q0 = qi << 7; nkt = qi + 1;
        qb = qr + ((size_t)bh * T_) * HD_;
        kb = kr + ((size_t)(b*HKV_ + kvh) * T_) * HD_;
        vb = vT + ((size_t)(b*HKV_ + kvh) * HD_) * T_;
    }
}

// ---------------- launch ----------------
extern "C" void kernel_launch(void* const* d_in, const int* in_sizes, int n_in,
                              void* d_out, int out_size) {
    const float* x  = (const float*)d_in[0];
    const float* Wq = (const float*)d_in[1];
    const float* Wk = (const float*)d_in[2];
    const float* Wv = (const float*)d_in[3];
    const float* Wo = (const float*)d_in[4];
    float* out = (float*)d_out;

    __half *xh, *wcatT, *worT, *qr, *kr, *vT, *attn;
    cudaGetSymbolAddress((void**)&xh,    g_xh);
    cudaGetSymbolAddress((void**)&wcatT, g_wcatT);
    cudaGetSymbolAddress((void**)&worT,  g_worT);
    cudaGetSymbolAddress((void**)&qr,    g_qr);
    cudaGetSymbolAddress((void**)&kr,    g_kr);
    cudaGetSymbolAddress((void**)&vT,    g_vT);
    cudaGetSymbolAddress((void**)&attn,  g_attn);

    rope_table_kernel<<<T_, 64>>>();

    // fp16 conversion of x; all weight transposes in one launch
    int n4x = MROWS*D_/4;
    conv_half<<<(n4x + 255)/256, 256>>>((const float4*)x, (__half2*)xh, n4x);
    trans_all<<<10240, 256>>>(Wq, Wk, Wv, Wo, wcatT, worT);

    // fused QKV projection + RoPE + layout (writes qr/kr/vT directly)
    cudaFuncSetAttribute(gemm_qkv, cudaFuncAttributeMaxDynamicSharedMemorySize, GM_SMEM);
    gemm_qkv<<<dim3(NQKV/128, MROWS/128), 256, GM_SMEM>>>(xh, wcatT, qr, kr, vT);

    // persistent fp16 flash attention (snake-scheduled work items)
    cudaFuncSetAttribute(flash_f16, cudaFuncAttributeMaxDynamicSharedMemorySize, FSM_BYTES);
    flash_f16<<<NSM, 256, FSM_BYTES>>>(qr, kr, vT, attn);

    // output projection (f32 out)
    cudaFuncSetAttribute(gemm_f16, cudaFuncAttributeMaxDynamicSharedMemorySize, GM_SMEM);
    gemm_f16<<<dim3(D_/128, MROWS/128), 256, GM_SMEM>>>(attn, worT, out, D_, D_);
}